// round 8
// baseline (speedup 1.0000x reference)
#include <cuda_runtime.h>
#include <math.h>

// q(row) = prod_i cos(pi/2 + 2*x_i) = prod_i sin(2*x_i)   (8 factors, sign cancels)
// out[row] = { scale*q, -scale*q }
//
// Persistent grid-stride version: exactly one wave of CTAs (148 SMs x 8 blocks),
// each warp loops over 128-row tiles. Per tile:
//   - 8 front-batched, fully coalesced LDG.128 per thread (MLP=8, streaming)
//   - shfl_xor(1) merges the two half-row partial products
//   - smem transpose (128 floats/warp) -> 2 fully coalesced STG.128 per thread

__device__ __forceinline__ float prod4(float4 f)
{
    return __sinf(2.0f * f.x) * __sinf(2.0f * f.y) *
           __sinf(2.0f * f.z) * __sinf(2.0f * f.w);
}

__global__ __launch_bounds__(256) void qnn_kernel(
    const float4* __restrict__ x4,    // [B*2] float4
    const float* __restrict__ scale,  // [1]
    float4* __restrict__ out4,        // [B/2] float4
    int ntiles,                       // B / 128
    int nwarps)                       // gridDim.x * 8
{
    __shared__ float srow[8][128];    // per-warp row values (4 KB)

    int warp = threadIdx.x >> 5;
    int lane = threadIdx.x & 31;
    int gw0  = blockIdx.x * 8 + warp;
    int k    = lane >> 1;
    float s  = *scale;

    float* my_srow = srow[warp];
    const float2* sr2 = reinterpret_cast<const float2*>(my_srow);

    for (int tile = gw0; tile < ntiles; tile += nwarps) {
        size_t xbase = (size_t)tile * 256;        // float4 index

        float4 f0 = __ldcs(&x4[xbase +   0 + lane]);
        float4 f1 = __ldcs(&x4[xbase +  32 + lane]);
        float4 f2 = __ldcs(&x4[xbase +  64 + lane]);
        float4 f3 = __ldcs(&x4[xbase +  96 + lane]);
        float4 f4 = __ldcs(&x4[xbase + 128 + lane]);
        float4 f5 = __ldcs(&x4[xbase + 160 + lane]);
        float4 f6 = __ldcs(&x4[xbase + 192 + lane]);
        float4 f7 = __ldcs(&x4[xbase + 224 + lane]);

        float p0 = prod4(f0), p1 = prod4(f1), p2 = prod4(f2), p3 = prod4(f3);
        float p4 = prod4(f4), p5 = prod4(f5), p6 = prod4(f6), p7 = prod4(f7);

        float v0 = p0 * __shfl_xor_sync(0xffffffffu, p0, 1);
        float v1 = p1 * __shfl_xor_sync(0xffffffffu, p1, 1);
        float v2 = p2 * __shfl_xor_sync(0xffffffffu, p2, 1);
        float v3 = p3 * __shfl_xor_sync(0xffffffffu, p3, 1);
        float v4 = p4 * __shfl_xor_sync(0xffffffffu, p4, 1);
        float v5 = p5 * __shfl_xor_sync(0xffffffffu, p5, 1);
        float v6 = p6 * __shfl_xor_sync(0xffffffffu, p6, 1);
        float v7 = p7 * __shfl_xor_sync(0xffffffffu, p7, 1);

        if ((lane & 1) == 0) {
            my_srow[k      ] = v0;
            my_srow[k +  16] = v1;
            my_srow[k +  32] = v2;
            my_srow[k +  48] = v3;
            my_srow[k +  64] = v4;
            my_srow[k +  80] = v5;
            my_srow[k +  96] = v6;
            my_srow[k + 112] = v7;
        }
        __syncwarp();

        float2 ra = sr2[lane];
        float2 rb = sr2[lane + 32];
        __syncwarp();   // protect srow against next-iteration overwrite

        float a0 = s * ra.x, a1 = s * ra.y;
        float b0 = s * rb.x, b1 = s * rb.y;

        __stcs(&out4[(size_t)tile * 64 + lane],      make_float4(a0, -a0, a1, -a1));
        __stcs(&out4[(size_t)tile * 64 + 32 + lane], make_float4(b0, -b0, b1, -b1));
    }
}

extern "C" void kernel_launch(void* const* d_in, const int* in_sizes, int n_in,
                              void* d_out, int out_size)
{
    const float* x     = (const float*)d_in[0];  // [B, 8] float32
    // d_in[1] = weights (unused)
    const float* scale = (const float*)d_in[2];  // scalar float32

    int B = in_sizes[0] / 8;                     // 4194304
    int ntiles = B / 128;                        // 32768 (B divisible by 128)

    int blocks = 148 * 8;                        // one full wave at occ=8
    int nwarps = blocks * 8;

    qnn_kernel<<<blocks, 256>>>((const float4*)x, scale, (float4*)d_out,
                                ntiles, nwarps);
}

// round 10
// speedup vs baseline: 1.0100x; 1.0100x over previous
#include <cuda_runtime.h>
#include <math.h>

// q(row) = prod_i cos(pi/2 + 2*x_i) = prod_i sin(2*x_i)   (8 factors, sign cancels)
// out[row] = { scale*q, -scale*q }
//
// R6 structure (best), 512-thread blocks:
//   - each warp owns 128 consecutive rows = 256 consecutive float4s of x
//   - 8 front-batched, fully coalesced LDG.128 per thread (MLP=8, streaming)
//   - shfl_xor(1) merges the two half-row partial products
//   - smem transpose (128 floats/warp) -> 2 fully coalesced STG.128 per thread

__device__ __forceinline__ float prod4(float4 f)
{
    return __sinf(2.0f * f.x) * __sinf(2.0f * f.y) *
           __sinf(2.0f * f.z) * __sinf(2.0f * f.w);
}

__global__ __launch_bounds__(512) void qnn_kernel(
    const float4* __restrict__ x4,    // [B*2] float4
    const float* __restrict__ scale,  // [1]
    float4* __restrict__ out4,        // [B/2] float4
    int B)
{
    __shared__ float srow[16][128];   // per-warp row values (8 KB total)

    int warp = threadIdx.x >> 5;
    int lane = threadIdx.x & 31;
    int gw   = blockIdx.x * 16 + warp;      // warp owns rows [gw*128, gw*128+128)
    if (gw * 128 >= B) return;

    size_t xbase = (size_t)gw * 256;        // float4 index

    // 8 coalesced, front-batched 16B streaming loads
    float4 f0 = __ldcs(&x4[xbase +   0 + lane]);
    float4 f1 = __ldcs(&x4[xbase +  32 + lane]);
    float4 f2 = __ldcs(&x4[xbase +  64 + lane]);
    float4 f3 = __ldcs(&x4[xbase +  96 + lane]);
    float4 f4 = __ldcs(&x4[xbase + 128 + lane]);
    float4 f5 = __ldcs(&x4[xbase + 160 + lane]);
    float4 f6 = __ldcs(&x4[xbase + 192 + lane]);
    float4 f7 = __ldcs(&x4[xbase + 224 + lane]);

    float s = *scale;

    float p0 = prod4(f0), p1 = prod4(f1), p2 = prod4(f2), p3 = prod4(f3);
    float p4 = prod4(f4), p5 = prod4(f5), p6 = prod4(f6), p7 = prod4(f7);

    // float4 #(xbase + c*32 + lane) is half (lane&1) of local row c*16 + (lane>>1)
    float v0 = p0 * __shfl_xor_sync(0xffffffffu, p0, 1);
    float v1 = p1 * __shfl_xor_sync(0xffffffffu, p1, 1);
    float v2 = p2 * __shfl_xor_sync(0xffffffffu, p2, 1);
    float v3 = p3 * __shfl_xor_sync(0xffffffffu, p3, 1);
    float v4 = p4 * __shfl_xor_sync(0xffffffffu, p4, 1);
    float v5 = p5 * __shfl_xor_sync(0xffffffffu, p5, 1);
    float v6 = p6 * __shfl_xor_sync(0xffffffffu, p6, 1);
    float v7 = p7 * __shfl_xor_sync(0xffffffffu, p7, 1);

    int k = lane >> 1;
    if ((lane & 1) == 0) {
        srow[warp][k      ] = v0;
        srow[warp][k +  16] = v1;
        srow[warp][k +  32] = v2;
        srow[warp][k +  48] = v3;
        srow[warp][k +  64] = v4;
        srow[warp][k +  80] = v5;
        srow[warp][k +  96] = v6;
        srow[warp][k + 112] = v7;
    }
    __syncwarp();

    // lane l emits rows (2l, 2l+1) and (64+2l, 64+2l+1): two coalesced float4 stores
    const float2* sr2 = reinterpret_cast<const float2*>(srow[warp]);
    float2 ra = sr2[lane];
    float2 rb = sr2[lane + 32];

    float a0 = s * ra.x, a1 = s * ra.y;
    float b0 = s * rb.x, b1 = s * rb.y;

    __stcs(&out4[(size_t)gw * 64 + lane],      make_float4(a0, -a0, a1, -a1));
    __stcs(&out4[(size_t)gw * 64 + 32 + lane], make_float4(b0, -b0, b1, -b1));
}

extern "C" void kernel_launch(void* const* d_in, const int* in_sizes, int n_in,
                              void* d_out, int out_size)
{
    const float* x     = (const float*)d_in[0];  // [B, 8] float32
    // d_in[1] = weights (unused)
    const float* scale = (const float*)d_in[2];  // scalar float32

    int B = in_sizes[0] / 8;                     // 4194304; divisible by 2048
    int rows_per_block = 2048;                   // 16 warps * 128 rows
    int blocks = (B + rows_per_block - 1) / rows_per_block;

    qnn_kernel<<<blocks, 512>>>((const float4*)x, scale, (float4*)d_out, B);
}

// round 11
// speedup vs baseline: 1.1532x; 1.1418x over previous
#include <cuda_runtime.h>
#include <math.h>

// q(row) = prod_i cos(pi/2 + 2*x_i) = prod_i sin(2*x_i)   (8 factors, sign cancels)
// out[row] = { scale*q, -scale*q }
//
// Final (R6) structure — best measured: 4096 blocks x 256 threads.
//   - each warp owns 128 consecutive rows = 256 consecutive float4s of x
//   - 8 front-batched, fully coalesced LDG.128 per thread (MLP=8, streaming)
//   - shfl_xor(1) merges the two half-row partial products
//   - smem transpose (128 floats/warp) -> 2 fully coalesced STG.128 per thread

__device__ __forceinline__ float prod4(float4 f)
{
    return __sinf(2.0f * f.x) * __sinf(2.0f * f.y) *
           __sinf(2.0f * f.z) * __sinf(2.0f * f.w);
}

__global__ __launch_bounds__(256) void qnn_kernel(
    const float4* __restrict__ x4,    // [B*2] float4
    const float* __restrict__ scale,  // [1]
    float4* __restrict__ out4,        // [B/2] float4
    int B)
{
    __shared__ float srow[8][128];    // per-warp row values (4 KB total)

    int warp = threadIdx.x >> 5;
    int lane = threadIdx.x & 31;
    int gw   = blockIdx.x * 8 + warp;       // warp owns rows [gw*128, gw*128+128)
    if (gw * 128 >= B) return;

    size_t xbase = (size_t)gw * 256;        // float4 index

    // 8 coalesced, front-batched 16B streaming loads
    float4 f0 = __ldcs(&x4[xbase +   0 + lane]);
    float4 f1 = __ldcs(&x4[xbase +  32 + lane]);
    float4 f2 = __ldcs(&x4[xbase +  64 + lane]);
    float4 f3 = __ldcs(&x4[xbase +  96 + lane]);
    float4 f4 = __ldcs(&x4[xbase + 128 + lane]);
    float4 f5 = __ldcs(&x4[xbase + 160 + lane]);
    float4 f6 = __ldcs(&x4[xbase + 192 + lane]);
    float4 f7 = __ldcs(&x4[xbase + 224 + lane]);

    float s = *scale;

    float p0 = prod4(f0), p1 = prod4(f1), p2 = prod4(f2), p3 = prod4(f3);
    float p4 = prod4(f4), p5 = prod4(f5), p6 = prod4(f6), p7 = prod4(f7);

    // float4 #(xbase + c*32 + lane) is half (lane&1) of local row c*16 + (lane>>1)
    float v0 = p0 * __shfl_xor_sync(0xffffffffu, p0, 1);
    float v1 = p1 * __shfl_xor_sync(0xffffffffu, p1, 1);
    float v2 = p2 * __shfl_xor_sync(0xffffffffu, p2, 1);
    float v3 = p3 * __shfl_xor_sync(0xffffffffu, p3, 1);
    float v4 = p4 * __shfl_xor_sync(0xffffffffu, p4, 1);
    float v5 = p5 * __shfl_xor_sync(0xffffffffu, p5, 1);
    float v6 = p6 * __shfl_xor_sync(0xffffffffu, p6, 1);
    float v7 = p7 * __shfl_xor_sync(0xffffffffu, p7, 1);

    int k = lane >> 1;
    if ((lane & 1) == 0) {
        srow[warp][k      ] = v0;
        srow[warp][k +  16] = v1;
        srow[warp][k +  32] = v2;
        srow[warp][k +  48] = v3;
        srow[warp][k +  64] = v4;
        srow[warp][k +  80] = v5;
        srow[warp][k +  96] = v6;
        srow[warp][k + 112] = v7;
    }
    __syncwarp();

    // lane l emits rows (2l, 2l+1) and (64+2l, 64+2l+1): two coalesced float4 stores
    const float2* sr2 = reinterpret_cast<const float2*>(srow[warp]);
    float2 ra = sr2[lane];
    float2 rb = sr2[lane + 32];

    float a0 = s * ra.x, a1 = s * ra.y;
    float b0 = s * rb.x, b1 = s * rb.y;

    __stcs(&out4[(size_t)gw * 64 + lane],      make_float4(a0, -a0, a1, -a1));
    __stcs(&out4[(size_t)gw * 64 + 32 + lane], make_float4(b0, -b0, b1, -b1));
}

extern "C" void kernel_launch(void* const* d_in, const int* in_sizes, int n_in,
                              void* d_out, int out_size)
{
    const float* x     = (const float*)d_in[0];  // [B, 8] float32
    // d_in[1] = weights (unused)
    const float* scale = (const float*)d_in[2];  // scalar float32

    int B = in_sizes[0] / 8;                     // 4194304; divisible by 1024
    int rows_per_block = 1024;                   // 8 warps * 128 rows
    int blocks = (B + rows_per_block - 1) / rows_per_block;

    qnn_kernel<<<blocks, 256>>>((const float4*)x, scale, (float4*)d_out, B);
}